// round 6
// baseline (speedup 1.0000x reference)
#include <cuda_runtime.h>
#include <cstdint>

// PPEG one-kernel: cls passthrough + combined (7x7+5x5+3x3+identity) depthwise
// conv as a single folded 7x7. Persistent-column CTAs with a 22-slot smem ring,
// cp.async pipelined staging, weights in registers.

#define CH   512
#define HW   64
#define NTOK 4097

#define TX   16                 // column width (output px)
#define IW   22                 // staged row width = TX+6
#define CG   64                 // channels per CTA
#define RING 22                 // ring slots = window(14) + advance(8)
#define ROWF (IW*CG)            // floats per ring row (1408)

typedef unsigned long long ULL;

__device__ __forceinline__ ULL ffma2(ULL a, ULL b, ULL c) {
    ULL d;
    asm("fma.rn.f32x2 %0, %1, %2, %3;" : "=l"(d) : "l"(a), "l"(b), "l"(c));
    return d;
}
__device__ __forceinline__ uint32_t smem_u32(const void* p) {
    uint32_t a;
    asm("{ .reg .u64 t; cvta.to.shared.u64 t, %1; cvt.u32.u64 %0, t; }"
        : "=r"(a) : "l"(p));
    return a;
}
__device__ __forceinline__ void cpa16(uint32_t dst, const void* src, int src_sz) {
    asm volatile("cp.async.ca.shared.global [%0], [%1], 16, %2;"
                 :: "r"(dst), "l"(src), "r"(src_sz) : "memory");
}

extern __shared__ float s_in[];  // RING * ROWF floats = 123,904 B

__global__ void __launch_bounds__(256, 1)
ppeg_all(const float* __restrict__ x,
         const float* __restrict__ w7, const float* __restrict__ b7,
         const float* __restrict__ w5, const float* __restrict__ b5,
         const float* __restrict__ w3, const float* __restrict__ b3,
         float* __restrict__ out) {
    const int tid  = threadIdx.x;
    const int lane = tid & 31;
    const int warp = tid >> 5;                 // 0..7
    const int wx = warp & 1;                   // 0..1
    const int wy = warp >> 1;                  // 0..3
    const int wy2 = wy * 2;

    const int bxp    = blockIdx.x * TX;        // column x origin
    const int ystart = blockIdx.y * 32;        // half-column y origin
    const int b  = blockIdx.z >> 3;
    const int cg = blockIdx.z & 7;
    const int cb = cg * CG;
    const int c0 = cb + lane * 2;              // this thread's channel pair

    const float* xb = x + ((size_t)b * NTOK + 1) * CH + cb;
    const uint32_t sbase = smem_u32(s_in);

    // staging thread map: c4 = 16B channel chunk, j0 = column
    const int c4 = tid & 15;
    const int j0 = tid >> 4;                   // 0..15; cols j0 and j0+16 (j0<6)

    // ---- stage one ring row: local row index iy (global), slot (0..21) ----
    auto stage_row = [&](int iy, int slot) {
        const bool yok = ((unsigned)iy < (unsigned)HW);
        const int iyc = yok ? iy : 0;
        #pragma unroll
        for (int jj = 0; jj < 2; ++jj) {
            const int j = j0 + jj * 16;
            if (jj == 0 || j0 < IW - 16) {
                const int ix = bxp - 3 + j;
                const bool ok = yok && ((unsigned)ix < (unsigned)HW);
                const float* g = xb + ((size_t)iyc * HW + (ok ? ix : 0)) * CH + c4 * 4;
                const uint32_t s = sbase + (uint32_t)((slot * ROWF + j * CG + c4 * 4) * 4);
                cpa16(s, g, ok ? 16 : 0);
            }
        }
    };

    // ---- cls token passthrough (128 designated CTAs) ----
    if (blockIdx.x == 0 && blockIdx.y == 0 && tid < 32) {
        const size_t off = (size_t)b * NTOK * CH + cb + tid * 2;
        *reinterpret_cast<ULL*>(out + off) =
            *reinterpret_cast<const ULL*>(x + off);
    }

    // ---- prologue: stage window rows L=0..13 (iy = ystart-3+L) ----
    #pragma unroll
    for (int L = 0; L < 14; ++L)
        stage_row(ystart - 3 + L, L);
    asm volatile("cp.async.commit_group;" ::: "memory");

    // ---- fold weights + bias into registers (overlaps prologue transfer) ----
    ULL wreg[49];
    float2* wf = reinterpret_cast<float2*>(wreg);
    #pragma unroll
    for (int t = 0; t < 49; ++t) {
        const int ky = t / 7, kx = t % 7;
        float vx = w7[(size_t)c0 * 49 + t];
        float vy = w7[(size_t)(c0 + 1) * 49 + t];
        if (ky >= 1 && ky <= 5 && kx >= 1 && kx <= 5) {
            const int t5 = (ky - 1) * 5 + (kx - 1);
            vx += w5[(size_t)c0 * 25 + t5];
            vy += w5[(size_t)(c0 + 1) * 25 + t5];
        }
        if (ky >= 2 && ky <= 4 && kx >= 2 && kx <= 4) {
            const int t3 = (ky - 2) * 3 + (kx - 2);
            vx += w3[(size_t)c0 * 9 + t3];
            vy += w3[(size_t)(c0 + 1) * 9 + t3];
        }
        if (t == 24) { vx += 1.0f; vy += 1.0f; }    // identity term
        float2 v; v.x = vx; v.y = vy;
        wf[t] = v;
    }
    ULL bias;
    {
        float2 bb;
        bb.x = b7[c0] + b5[c0] + b3[c0];
        bb.y = b7[c0 + 1] + b5[c0 + 1] + b3[c0 + 1];
        bias = *reinterpret_cast<ULL*>(&bb);
    }

    asm volatile("cp.async.wait_group 0;" ::: "memory");
    __syncthreads();

    float* ob = out + ((size_t)b * NTOK + 1) * CH + cb + lane * 2;
    const int xoff = wx * 8;
    const float* winbase = s_in + xoff * CG + lane * 2;

    int wb = 0;                                // window base slot = (8s) % 22
    int ys = ystart - 3;                       // global iy of window row 0

    #pragma unroll 1
    for (int s = 0; s < 4; ++s) {
        // -- issue staging for next step (slots wb+14..wb+21 mod 22) --
        if (s < 3) {
            int tb = wb + 14; if (tb >= RING) tb -= RING;
            #pragma unroll
            for (int r = 0; r < 8; ++r) {
                int slot = tb + r; if (slot >= RING) slot -= RING;
                stage_row(ys + 14 + r, slot);
            }
        }
        asm volatile("cp.async.commit_group;" ::: "memory");

        // -- compute 16x8 outputs: thread = 8 wide x 2 tall --
        ULL acc[2][8];
        #pragma unroll
        for (int ry = 0; ry < 2; ++ry)
            #pragma unroll
            for (int rx = 0; rx < 8; ++rx)
                acc[ry][rx] = bias;

        #pragma unroll
        for (int k = 0; k < 8; ++k) {
            int slot = wb + wy2 + k; if (slot >= RING) slot -= RING;
            const float* rowp = winbase + slot * ROWF;
            ULL rw[14];
            #pragma unroll
            for (int i = 0; i < 14; ++i)
                rw[i] = *reinterpret_cast<const ULL*>(&rowp[i * CG]);

            if (k <= 6) {                      // output row 0: ky = k
                #pragma unroll
                for (int kx = 0; kx < 7; ++kx)
                    #pragma unroll
                    for (int rx = 0; rx < 8; ++rx)
                        acc[0][rx] = ffma2(rw[rx + kx], wreg[k * 7 + kx], acc[0][rx]);
            }
            if (k >= 1) {                      // output row 1: ky = k-1
                #pragma unroll
                for (int kx = 0; kx < 7; ++kx)
                    #pragma unroll
                    for (int rx = 0; rx < 8; ++rx)
                        acc[1][rx] = ffma2(rw[rx + kx], wreg[(k - 1) * 7 + kx], acc[1][rx]);
            }
        }

        // -- store 16 ULL --
        const int ybase = ys + 3 + wy2;        // = ystart + 8s + wy*2
        #pragma unroll
        for (int ry = 0; ry < 2; ++ry)
            #pragma unroll
            for (int rx = 0; rx < 8; ++rx) {
                const size_t p = (size_t)(ybase + ry) * HW + (bxp + xoff + rx);
                *reinterpret_cast<ULL*>(&ob[p * CH]) = acc[ry][rx];
            }

        // -- retire staging group, publish, advance ring --
        asm volatile("cp.async.wait_group 0;" ::: "memory");
        __syncthreads();
        wb += 8; if (wb >= RING) wb -= RING;
        ys += 8;
    }
}

// ---------------------------------------------------------------------------
extern "C" void kernel_launch(void* const* d_in, const int* in_sizes, int n_in,
                              void* d_out, int out_size) {
    const float* x  = (const float*)d_in[0];
    const float* w7 = (const float*)d_in[1];
    const float* b7 = (const float*)d_in[2];
    const float* w5 = (const float*)d_in[3];
    const float* b5 = (const float*)d_in[4];
    const float* w3 = (const float*)d_in[5];
    const float* b3 = (const float*)d_in[6];
    float* out = (float*)d_out;

    const int smem = RING * ROWF * (int)sizeof(float);   // 123,904 B
    cudaFuncSetAttribute(ppeg_all, cudaFuncAttributeMaxDynamicSharedMemorySize, smem);

    dim3 grid(HW / TX, 2, 16 * 8);             // (4, 2, 128) = 1024 CTAs
    ppeg_all<<<grid, 256, smem>>>(x, w7, b7, w5, b5, w3, b3, out);
}

// round 7
// speedup vs baseline: 1.2090x; 1.2090x over previous
#include <cuda_runtime.h>
#include <cstdint>

// PPEG: out[b,0,c] = x[b,0,c] (cls); out[b,1+p,c] = folded 7x7 depthwise conv
// (w7 + pad(w5) + pad(w3) + identity, bias b7+b5+b3) over the 64x64 map.
// R7 = R2 skeleton (direct LDG windows, weights in smem, no hot-path barriers)
// with a 16x8 tile (halo 2.41x) and 3 CTAs/SM (24 warps).

#define CH   512
#define HW   64
#define NTOK 4097

typedef unsigned long long ULL;

__device__ float g_weff[49 * CH];   // [tap][channel]
__device__ float g_bsum[CH];

// packed f32x2 FMA (sm_103a FFMA2 — only reachable via PTX)
__device__ __forceinline__ ULL ffma2(ULL a, ULL b, ULL c) {
    ULL d;
    asm("fma.rn.f32x2 %0, %1, %2, %3;" : "=l"(d) : "l"(a), "l"(b), "l"(c));
    return d;
}

// ---------------------------------------------------------------------------
// Kernel 1: weight fold + bias + cls copy, one launch.
__global__ void ppeg_prep(const float* __restrict__ w7, const float* __restrict__ b7,
                          const float* __restrict__ w5, const float* __restrict__ b5,
                          const float* __restrict__ w3, const float* __restrict__ b3,
                          const float* __restrict__ x, float* __restrict__ out) {
    const int bid = blockIdx.x;
    const int tid = threadIdx.x;
    if (bid < 98) {
        const int i = bid * 256 + tid;        // 0 .. 25087 = 512*49
        const int c = i / 49;
        const int t = i % 49;
        const int ky = t / 7, kx = t % 7;
        float v = w7[c * 49 + t];
        if (ky >= 1 && ky <= 5 && kx >= 1 && kx <= 5)
            v += w5[c * 25 + (ky - 1) * 5 + (kx - 1)];
        if (ky >= 2 && ky <= 4 && kx >= 2 && kx <= 4)
            v += w3[c * 9 + (ky - 2) * 3 + (kx - 2)];
        if (t == 24) v += 1.0f;               // identity (residual) term
        g_weff[t * CH + c] = v;
    } else if (bid < 100) {
        const int c = (bid - 98) * 256 + tid;
        g_bsum[c] = b7[c] + b5[c] + b3[c];
    } else {
        const int j = (bid - 100) * 256 + tid;   // cls: 16*512 floats
        const int b = j >> 9;
        const int cc = j & 511;
        const size_t off = (size_t)b * NTOK * CH + cc;
        out[off] = x[off];
    }
}

// ---------------------------------------------------------------------------
// Kernel 2: folded 7x7 depthwise conv.
//   lane   = channel pair (64 ch per block) -> 256B coalesced accesses
//   thread = 8x2 output pixels; warps 2x4 -> block tile 16x8 pixels
//   weights + bias staged to smem once; inner loop = LDG window + LDS wk + FFMA2
__global__ void __launch_bounds__(256, 3)
ppeg_conv(const float* __restrict__ x, float* __restrict__ out) {
    const int lane = threadIdx.x & 31;
    const int warp = threadIdx.x >> 5;         // 0..7
    const int wx = warp & 1;
    const int wy = warp >> 1;                  // 0..3
    const int x0 = blockIdx.x * 16 + wx * 8;   // RX=8 output cols per thread
    const int y0 = blockIdx.y * 8 + wy * 2;    // RY=2 output rows per thread
    const int b  = blockIdx.z >> 3;
    const int cg = blockIdx.z & 7;
    const int cb = cg * 64;
    const int c  = cb + lane * 2;

    // Stage this channel group's folded weights + bias into SMEM (coalesced).
    __shared__ __align__(16) float sw[49 * 64];
    __shared__ __align__(16) float sb[64];
    for (int i = threadIdx.x; i < 49 * 64; i += 256) {
        const int t  = i >> 6;
        const int cc = i & 63;
        sw[i] = g_weff[t * CH + cb + cc];
    }
    if (threadIdx.x < 64) sb[threadIdx.x] = g_bsum[cb + threadIdx.x];
    __syncthreads();

    const ULL bias = *reinterpret_cast<const ULL*>(&sb[lane * 2]);

    ULL acc[2][8];
    #pragma unroll
    for (int ry = 0; ry < 2; ++ry)
        #pragma unroll
        for (int rx = 0; rx < 8; ++rx)
            acc[ry][rx] = bias;

    const float* xb = x + ((size_t)b * NTOK + 1) * CH + c;
    const float* swp = &sw[lane * 2];

    // Sliding row window: 8 input rows feed the 2 output rows (RY+6).
    #pragma unroll
    for (int riy = 0; riy < 8; ++riy) {
        const int iy = y0 - 3 + riy;
        const bool yok = ((unsigned)iy < (unsigned)HW);
        const float* row = xb + (size_t)iy * HW * CH;

        ULL rw[14];
        #pragma unroll
        for (int i = 0; i < 14; ++i) {
            const int xc = x0 - 3 + i;
            rw[i] = (yok && (unsigned)xc < (unsigned)HW)
                  ? *reinterpret_cast<const ULL*>(&row[(size_t)xc * CH])
                  : 0ULL;
        }

        #pragma unroll
        for (int ky = 0; ky < 7; ++ky) {
            const int ry = riy - ky;           // compile-time after full unroll
            if (ry == 0 || ry == 1) {
                #pragma unroll
                for (int kx = 0; kx < 7; ++kx) {
                    const ULL wk = *reinterpret_cast<const ULL*>(
                        &swp[(ky * 7 + kx) * 64]);
                    #pragma unroll
                    for (int rx = 0; rx < 8; ++rx)
                        acc[ry][rx] = ffma2(rw[rx + kx], wk, acc[ry][rx]);
                }
            }
        }
    }

    float* ob = out + ((size_t)b * NTOK + 1) * CH + c;
    #pragma unroll
    for (int ry = 0; ry < 2; ++ry)
        #pragma unroll
        for (int rx = 0; rx < 8; ++rx) {
            const size_t p = (size_t)(y0 + ry) * HW + (x0 + rx);
            *reinterpret_cast<ULL*>(&ob[p * CH]) = acc[ry][rx];
        }
}

// ---------------------------------------------------------------------------
extern "C" void kernel_launch(void* const* d_in, const int* in_sizes, int n_in,
                              void* d_out, int out_size) {
    const float* x  = (const float*)d_in[0];
    const float* w7 = (const float*)d_in[1];
    const float* b7 = (const float*)d_in[2];
    const float* w5 = (const float*)d_in[3];
    const float* b5 = (const float*)d_in[4];
    const float* w3 = (const float*)d_in[5];
    const float* b3 = (const float*)d_in[6];
    float* out = (float*)d_out;

    ppeg_prep<<<132, 256>>>(w7, b7, w5, b5, w3, b3, x, out);
    dim3 grid(4, 8, 16 * 8);                   // 16x8 tiles
    ppeg_conv<<<grid, 256>>>(x, out);
}